// round 5
// baseline (speedup 1.0000x reference)
#include <cuda_runtime.h>
#include <cstdint>
#include <cstddef>

#define BB 4
#define NN 512
#define DD 128
#define DH 64

// Scratch (no allocations allowed -> __device__ globals)
__device__ float g_Q [BB*NN*DH];
__device__ float g_K [BB*NN*DH];
__device__ float g_V [BB*NN*DH];
__device__ float g_Ni[BB*NN*DH];
__device__ float g_Nj[BB*NN*DH];
__device__ float g_A [BB*NN*NN];
__device__ float g_M [BB*NN];
__device__ float g_R [BB*NN];

// Packed fp32x2 FMA (sm_103a; 2x FFMA throughput vs 3-reg FFMA)
__device__ __forceinline__ float2 ffma2(float2 a, float2 b, float2 c) {
    unsigned long long ua = *reinterpret_cast<unsigned long long*>(&a);
    unsigned long long ub = *reinterpret_cast<unsigned long long*>(&b);
    unsigned long long uc = *reinterpret_cast<unsigned long long*>(&c);
    unsigned long long ud;
    asm("fma.rn.f32x2 %0, %1, %2, %3;" : "=l"(ud) : "l"(ua), "l"(ub), "l"(uc));
    return *reinterpret_cast<float2*>(&ud);
}

// ---------------------------------------------------------------------------
// Kernel 1: Q/K/V/Ni/Nj projections. 4 rows per block, 5 mats x 64 cols = 320 thr
// Ni absorbs be (with binary masks: e_out = m_i*m_j*(E_raw+be + Ni_raw + Nj_raw)).
// ---------------------------------------------------------------------------
__global__ __launch_bounds__(320) void proj_kernel(
    const float* __restrict__ x, const float* __restrict__ mask,
    const float* __restrict__ Wq, const float* __restrict__ bq,
    const float* __restrict__ Wk, const float* __restrict__ bk,
    const float* __restrict__ Wv, const float* __restrict__ bv,
    const float* __restrict__ Wni, const float* __restrict__ bni,
    const float* __restrict__ Wnj, const float* __restrict__ bnj,
    const float* __restrict__ be)
{
    __shared__ float xS[4][DD];
    int r0  = blockIdx.x * 4;
    int tid = threadIdx.x;
    for (int idx = tid; idx < 4 * DD; idx += 320)
        xS[idx >> 7][idx & 127] = x[r0 * DD + idx];
    __syncthreads();

    int mat = tid / 64;
    int d   = tid & 63;
    const float* W; float bias; float* dst; bool domask;
    switch (mat) {
        case 0:  W = Wq;  bias = bq[d];            dst = g_Q;  domask = true;  break;
        case 1:  W = Wk;  bias = bk[d];            dst = g_K;  domask = true;  break;
        case 2:  W = Wv;  bias = bv[d];            dst = g_V;  domask = true;  break;
        case 3:  W = Wni; bias = bni[d] + be[d];   dst = g_Ni; domask = false; break;
        default: W = Wnj; bias = bnj[d];           dst = g_Nj; domask = false; break;
    }
    float a0 = bias, a1 = bias, a2 = bias, a3 = bias;
    #pragma unroll 8
    for (int c = 0; c < DD; c++) {
        float wv = __ldg(&W[c * 64 + d]);
        a0 += xS[0][c] * wv;
        a1 += xS[1][c] * wv;
        a2 += xS[2][c] * wv;
        a3 += xS[3][c] * wv;
    }
    float acc[4] = {a0, a1, a2, a3};
    #pragma unroll
    for (int r = 0; r < 4; r++) {
        int row = r0 + r;
        float m = domask ? mask[row] : 1.0f;
        dst[row * 64 + d] = acc[r] * m;
    }
}

// ---------------------------------------------------------------------------
// Kernel 2: fused  E = e@We  ->  e_out = (Ni+Nj+E)*m  -> write e_out,
//           and raw attention logits A[b,i,j] = sum_d(Q*e_out*K)/8.
// Block = 128 thr (4 warps), handles one (b,i) row x 64 j's.
// Each warp: 2 groups of 8 pairs. Lane l owns output cols d=2l, 2l+1.
// WeT holds (even-c, odd-c) pairs so the FFMA2 multiplier needs no duplication:
// acc = (sum over even c, sum over odd c); final E_d = acc.x + acc.y.
// Inner loop per c-pair: 1 LDS.128 + 8 LDS.64(bcast) + 16 FFMA2 -> fma-pipe bound.
// ---------------------------------------------------------------------------
__global__ __launch_bounds__(128) void fused_kernel(
    const float* __restrict__ e, const float* __restrict__ We,
    const float* __restrict__ mask, float* __restrict__ eout)
{
    __shared__ float2 WeT[64][64];      // 32 KB: WeT[c2][d] = (We[2c2][d], We[2c2+1][d])
    __shared__ float  eS[4][8][DD];     // 16 KB: per-warp staged e rows

    int tid = threadIdx.x, w = tid >> 5, l = tid & 31;

    for (int idx = tid; idx < 64 * 64; idx += 128) {
        int c2 = idx >> 6, d = idx & 63;
        WeT[c2][d] = make_float2(We[(2 * c2) * 64 + d], We[(2 * c2 + 1) * 64 + d]);
    }

    int b = blockIdx.z, i = blockIdx.y;
    int jt = blockIdx.x * 64;
    int d0 = 2 * l;
    int rowi = b * NN + i;
    float2 q2  = *(const float2*)&g_Q [rowi * 64 + d0];
    float2 ni2 = *(const float2*)&g_Ni[rowi * 64 + d0];
    float  mi  = mask[rowi];
    __syncthreads();

    #pragma unroll 1
    for (int g = 0; g < 2; g++) {
        int j0 = jt + w * 16 + g * 8;
        const float4* esrc =
            reinterpret_cast<const float4*>(e + ((size_t)rowi * NN + j0) * DD);
        __syncwarp();
        #pragma unroll
        for (int p = 0; p < 8; p++) {
            float4 v = __ldcs(esrc + p * 32 + l);          // streaming: no L1 pollution
            *reinterpret_cast<float4*>(&eS[w][p][l * 4]) = v;
        }
        __syncwarp();

        float2 acc0[8], acc1[8];
        #pragma unroll
        for (int p = 0; p < 8; p++) {
            acc0[p] = make_float2(0.f, 0.f);
            acc1[p] = make_float2(0.f, 0.f);
        }

        #pragma unroll 4
        for (int c2 = 0; c2 < 64; c2++) {
            float4 wv = *reinterpret_cast<const float4*>(&WeT[c2][d0]); // cols d0,d0+1
            float2 w0 = make_float2(wv.x, wv.y);
            float2 w1 = make_float2(wv.z, wv.w);
            #pragma unroll
            for (int p = 0; p < 8; p++) {
                float2 e2 = *reinterpret_cast<const float2*>(&eS[w][p][2 * c2]);
                acc0[p] = ffma2(e2, w0, acc0[p]);
                acc1[p] = ffma2(e2, w1, acc1[p]);
            }
        }

        #pragma unroll
        for (int p = 0; p < 8; p++) {
            int j = j0 + p;
            int rowj = b * NN + j;
            float2 nj2 = *(const float2*)&g_Nj[rowj * 64 + d0];
            float2 k2  = *(const float2*)&g_K [rowj * 64 + d0];
            float  mj  = mask[rowj];
            float  me  = mi * mj;
            float  e0  = (acc0[p].x + acc0[p].y + ni2.x + nj2.x) * me;
            float  e1  = (acc1[p].x + acc1[p].y + ni2.y + nj2.y) * me;
            *reinterpret_cast<float2*>(
                &eout[(((size_t)rowi) * NN + j) * 64 + d0]) = make_float2(e0, e1);

            float part = e0 * q2.x * k2.x + e1 * q2.y * k2.y;
            #pragma unroll
            for (int off = 16; off; off >>= 1)
                part += __shfl_xor_sync(0xffffffffu, part, off);
            if (l == 0)
                g_A[(size_t)rowi * NN + j] = (me > 0.f) ? part * 0.125f : -1.0e9f;
        }
    }
}

// ---------------------------------------------------------------------------
// Kernel 3: softmax is over axis=1 (over i, per (b,j) column). Column max+sumexp.
// ---------------------------------------------------------------------------
__global__ void colstats_kernel()
{
    int b  = blockIdx.y;
    int j  = blockIdx.x * 32 + threadIdx.x;
    int ty = threadIdx.y;
    const float* A = g_A + (size_t)b * NN * NN;

    float m = -1e30f;
    for (int i = ty; i < NN; i += 8) m = fmaxf(m, A[(size_t)i * NN + j]);
    float s = 0.f;
    for (int i = ty; i < NN; i += 8) s += __expf(A[(size_t)i * NN + j] - m);

    __shared__ float sm[8][32], ss[8][32];
    sm[ty][threadIdx.x] = m;
    ss[ty][threadIdx.x] = s;
    __syncthreads();
    if (ty == 0) {
        float M = sm[0][threadIdx.x];
        #pragma unroll
        for (int t = 1; t < 8; t++) M = fmaxf(M, sm[t][threadIdx.x]);
        float S = 0.f;
        #pragma unroll
        for (int t = 0; t < 8; t++) S += ss[t][threadIdx.x] * __expf(sm[t][threadIdx.x] - M);
        g_M[b * NN + j] = M;
        g_R[b * NN + j] = 1.0f / S;
    }
}

// ---------------------------------------------------------------------------
// Kernel 4: x_out[b,i,:] = sum_j (exp(A-M_j)*R_j) * V[b,j,:], masked.
// ---------------------------------------------------------------------------
__global__ __launch_bounds__(64) void xout_kernel(
    const float* __restrict__ mask, float* __restrict__ xout)
{
    int b = blockIdx.y, i = blockIdx.x;
    int tid = threadIdx.x;
    __shared__ float pS[NN];
    const float* Arow = g_A + ((size_t)(b * NN + i)) * NN;
    for (int jj = tid; jj < NN; jj += 64)
        pS[jj] = __expf(Arow[jj] - g_M[b * NN + jj]) * g_R[b * NN + jj];
    __syncthreads();

    float a0 = 0.f, a1 = 0.f, a2 = 0.f, a3 = 0.f;
    const float* Vb = g_V + (size_t)b * NN * 64;
    for (int j = 0; j < NN; j += 4) {
        a0 += pS[j    ] * __ldg(&Vb[(j    ) * 64 + tid]);
        a1 += pS[j + 1] * __ldg(&Vb[(j + 1) * 64 + tid]);
        a2 += pS[j + 2] * __ldg(&Vb[(j + 2) * 64 + tid]);
        a3 += pS[j + 3] * __ldg(&Vb[(j + 3) * 64 + tid]);
    }
    xout[(size_t)(b * NN + i) * 64 + tid] = (a0 + a1 + a2 + a3) * mask[b * NN + i];
}

// ---------------------------------------------------------------------------
extern "C" void kernel_launch(void* const* d_in, const int* in_sizes, int n_in,
                              void* d_out, int out_size)
{
    const float* x    = (const float*)d_in[0];
    const float* e    = (const float*)d_in[1];
    const float* mask = (const float*)d_in[2];
    const float* Wq   = (const float*)d_in[3];
    const float* bq   = (const float*)d_in[4];
    const float* Wk   = (const float*)d_in[5];
    const float* bk   = (const float*)d_in[6];
    const float* We   = (const float*)d_in[7];
    const float* be   = (const float*)d_in[8];
    const float* Wv   = (const float*)d_in[9];
    const float* bv   = (const float*)d_in[10];
    const float* Wni  = (const float*)d_in[11];
    const float* bni  = (const float*)d_in[12];
    const float* Wnj  = (const float*)d_in[13];
    const float* bnj  = (const float*)d_in[14];

    float* xout = (float*)d_out;
    float* eout = (float*)d_out + (size_t)BB * NN * DH;

    proj_kernel<<<(BB * NN) / 4, 320>>>(x, mask, Wq, bq, Wk, bk, Wv, bv,
                                        Wni, bni, Wnj, bnj, be);

    dim3 g2(NN / 64, NN, BB);
    fused_kernel<<<g2, 128>>>(e, We, mask, eout);

    colstats_kernel<<<dim3(NN / 32, BB), dim3(32, 8)>>>();

    xout_kernel<<<dim3(NN, BB), 64>>>(mask, xout);
}

// round 10
// speedup vs baseline: 1.4336x; 1.4336x over previous
#include <cuda_runtime.h>
#include <cstdint>
#include <cstddef>

#define BB 4
#define NN 512
#define DD 128
#define DH 64

// Scratch (no allocations allowed -> __device__ globals)
__device__ float g_Q [BB*NN*DH];
__device__ float g_K [BB*NN*DH];
__device__ float g_V [BB*NN*DH];
__device__ float g_Ni[BB*NN*DH];
__device__ float g_Nj[BB*NN*DH];
__device__ float g_A [BB*NN*NN];
__device__ float g_M [BB*NN];
__device__ float g_R [BB*NN];

// We^T prepared: tf32(RN) bits, padded layout [128 rows (c)][72 cols (d, 64 used)]
#define WPAD 72
__device__ float g_WeB[DD * WPAD];

// ============================ helpers ============================
__device__ __forceinline__ uint32_t smem_u32(const void* p) {
    uint32_t a;
    asm("{ .reg .u64 t; cvta.to.shared.u64 t, %1; cvt.u32.u64 %0, t; }" : "=r"(a) : "l"(p));
    return a;
}
__device__ __forceinline__ void cp16(uint32_t dst, const void* src) {
    asm volatile("cp.async.cg.shared.global [%0], [%1], 16;" :: "r"(dst), "l"(src));
}
__device__ __forceinline__ uint32_t tf32_rna(float x) {
    uint32_t u;
    asm("cvt.rna.tf32.f32 %0, %1;" : "=r"(u) : "f"(x));
    return u;
}
__device__ __forceinline__ void mma_tf32(float& d0, float& d1, float& d2, float& d3,
                                         uint32_t a0, uint32_t a1, uint32_t a2, uint32_t a3,
                                         uint32_t b0, uint32_t b1) {
    asm volatile(
        "mma.sync.aligned.m16n8k8.row.col.f32.tf32.tf32.f32 "
        "{%0,%1,%2,%3}, {%4,%5,%6,%7}, {%8,%9}, {%0,%1,%2,%3};"
        : "+f"(d0), "+f"(d1), "+f"(d2), "+f"(d3)
        : "r"(a0), "r"(a1), "r"(a2), "r"(a3), "r"(b0), "r"(b1));
}

// ---------------------------------------------------------------------------
// Kernel 1: Q/K/V/Ni/Nj projections (Ni absorbs be).
// ---------------------------------------------------------------------------
__global__ __launch_bounds__(320) void proj_kernel(
    const float* __restrict__ x, const float* __restrict__ mask,
    const float* __restrict__ Wq, const float* __restrict__ bq,
    const float* __restrict__ Wk, const float* __restrict__ bk,
    const float* __restrict__ Wv, const float* __restrict__ bv,
    const float* __restrict__ Wni, const float* __restrict__ bni,
    const float* __restrict__ Wnj, const float* __restrict__ bnj,
    const float* __restrict__ be)
{
    __shared__ float xS[4][DD];
    int r0  = blockIdx.x * 4;
    int tid = threadIdx.x;
    for (int idx = tid; idx < 4 * DD; idx += 320)
        xS[idx >> 7][idx & 127] = x[r0 * DD + idx];
    __syncthreads();

    int mat = tid / 64;
    int d   = tid & 63;
    const float* W; float bias; float* dst; bool domask;
    switch (mat) {
        case 0:  W = Wq;  bias = bq[d];            dst = g_Q;  domask = true;  break;
        case 1:  W = Wk;  bias = bk[d];            dst = g_K;  domask = true;  break;
        case 2:  W = Wv;  bias = bv[d];            dst = g_V;  domask = true;  break;
        case 3:  W = Wni; bias = bni[d] + be[d];   dst = g_Ni; domask = false; break;
        default: W = Wnj; bias = bnj[d];           dst = g_Nj; domask = false; break;
    }
    float a0 = bias, a1 = bias, a2 = bias, a3 = bias;
    #pragma unroll 8
    for (int c = 0; c < DD; c++) {
        float wv = __ldg(&W[c * 64 + d]);
        a0 += xS[0][c] * wv;
        a1 += xS[1][c] * wv;
        a2 += xS[2][c] * wv;
        a3 += xS[3][c] * wv;
    }
    float acc[4] = {a0, a1, a2, a3};
    #pragma unroll
    for (int r = 0; r < 4; r++) {
        int row = r0 + r;
        float m = domask ? mask[row] : 1.0f;
        dst[row * 64 + d] = acc[r] * m;
    }
}

// ---------------------------------------------------------------------------
// Kernel 1b: We -> g_WeB: tf32-RN rounded, padded [128][72] (zero pad).
// ---------------------------------------------------------------------------
__global__ void prep_we_kernel(const float* __restrict__ We)
{
    int idx = blockIdx.x * 128 + threadIdx.x;     // 0 .. 9215
    int row = idx / WPAD;                          // c
    int col = idx - row * WPAD;                    // d (padded)
    uint32_t bits = 0;
    if (col < DH) bits = tf32_rna(We[row * DH + col]);
    g_WeB[idx] = __uint_as_float(bits);
}

// ---------------------------------------------------------------------------
// Kernel 2: fused  E = e@We (tf32 mma.sync) -> e_out + logits.
// One CTA per (b,i). 256 thr = 8 warps; warp w owns rows [(w>>1)*32, +32),
// cols [(w&1)*32, +32) of each 128j x 64d output tile.
// A tile (e rows) double-buffered in smem, pad 132 (conflict-free frags).
// B (We tf32) resident in smem, pad 72 (conflict-free frags).
// ---------------------------------------------------------------------------
#define APAD 132
#define OFF_WE   0
#define OFF_A0   (DD * WPAD)                       // 9216
#define OFF_A1   (OFF_A0 + 128 * APAD)             // 26112
#define OFF_PS   (OFF_A1 + 128 * APAD)             // 43008
#define SMEM_FLOATS (OFF_PS + 256)                 // 43264
#define SMEM_BYTES  (SMEM_FLOATS * 4)              // 173056

// FIXED: full 128x128 f32 tile (64 KB). 256 threads: warp covers one full
// 512B row (32 x cp16), 8 rows per pass, 16 passes.
__device__ __forceinline__ void load_tile(uint32_t dstbase, const float* __restrict__ src0,
                                          int tid)
{
    int c4 = tid & 31;          // float4 index within 512B row (0..31)
    int r0 = tid >> 5;          // 0..7
    const float* s = src0 + c4 * 4;
    #pragma unroll
    for (int k = 0; k < 16; k++) {
        int r = r0 + 8 * k;
        cp16(dstbase + (uint32_t)(r * APAD + c4 * 4) * 4, s + (size_t)r * DD);
    }
}

__global__ void __launch_bounds__(256, 1) fused_mma_kernel(
    const float* __restrict__ e, const float* __restrict__ mask,
    float* __restrict__ eout)
{
    extern __shared__ float smf[];
    float* WeS = smf + OFF_WE;
    float* pSm = smf + OFF_PS;                     // [128][2]
    uint32_t sb = smem_u32(smf);

    int tid  = threadIdx.x;
    int w    = tid >> 5, lane = tid & 31;
    int gid  = lane >> 2, tig = lane & 3;
    int wrow = (w >> 1) * 32;
    int wcol = (w & 1) * 32;

    int b = blockIdx.y, i = blockIdx.x;
    int rowi = b * NN + i;
    float mi = mask[rowi];

    // per-thread Q / Ni for its 8 owned columns
    float2 q2[4], ni2[4];
    #pragma unroll
    for (int nt = 0; nt < 4; nt++) {
        int d0 = wcol + 8 * nt + 2 * tig;
        q2[nt]  = *(const float2*)&g_Q [rowi * 64 + d0];
        ni2[nt] = *(const float2*)&g_Ni[rowi * 64 + d0];
    }

    // stage We (9216 floats = 2304 float4; 9 per thread) + tile 0
    {
        const char* wsrc = (const char*)g_WeB;
        #pragma unroll
        for (int k = 0; k < 9; k++) {
            uint32_t off = (uint32_t)(tid + k * 256) * 16;
            cp16(sb + OFF_WE * 4 + off, wsrc + off);
        }
    }
    const float* esrc = e + (size_t)rowi * NN * DD;
    load_tile(sb + OFF_A0 * 4, esrc, tid);
    asm volatile("cp.async.commit_group;" ::: "memory");

    #pragma unroll 1
    for (int t = 0; t < 4; t++) {
        if (t < 3) {
            load_tile(sb + (((t + 1) & 1) ? OFF_A1 : OFF_A0) * 4,
                      esrc + (size_t)(t + 1) * 128 * DD, tid);
            asm volatile("cp.async.commit_group;" ::: "memory");
            asm volatile("cp.async.wait_group 1;" ::: "memory");
        } else {
            asm volatile("cp.async.wait_group 0;" ::: "memory");
        }
        __syncthreads();

        const float* A = smf + ((t & 1) ? OFF_A1 : OFF_A0);
        const float* Ab = A + (wrow + gid) * APAD + tig;   // row gid, col tig
        const float* Bb = WeS + tig * WPAD + wcol + gid;   // k tig, n gid

        float acc[2][4][4];
        #pragma unroll
        for (int mt = 0; mt < 2; mt++)
            #pragma unroll
            for (int nt = 0; nt < 4; nt++)
                #pragma unroll
                for (int q = 0; q < 4; q++) acc[mt][nt][q] = 0.f;

        #pragma unroll
        for (int ks = 0; ks < 16; ks++) {
            const int c0 = 8 * ks;
            uint32_t aR[2][4];
            #pragma unroll
            for (int mt = 0; mt < 2; mt++) {
                const float* p = Ab + mt * 16 * APAD + c0;
                aR[mt][0] = tf32_rna(p[0]);
                aR[mt][1] = tf32_rna(p[8 * APAD]);
                aR[mt][2] = tf32_rna(p[4]);
                aR[mt][3] = tf32_rna(p[8 * APAD + 4]);
            }
            uint32_t bR[4][2];
            #pragma unroll
            for (int nt = 0; nt < 4; nt++) {
                const float* p = Bb + c0 * WPAD + 8 * nt;
                bR[nt][0] = __float_as_uint(p[0]);
                bR[nt][1] = __float_as_uint(p[4 * WPAD]);
            }
            #pragma unroll
            for (int mt = 0; mt < 2; mt++)
                #pragma unroll
                for (int nt = 0; nt < 4; nt++)
                    mma_tf32(acc[mt][nt][0], acc[mt][nt][1],
                             acc[mt][nt][2], acc[mt][nt][3],
                             aR[mt][0], aR[mt][1], aR[mt][2], aR[mt][3],
                             bR[nt][0], bR[nt][1]);
        }

        // ---- epilogue on fragments ----
        int jt = t * 128;
        #pragma unroll
        for (int mt = 0; mt < 2; mt++) {
            #pragma unroll
            for (int rr = 0; rr < 2; rr++) {
                int row  = wrow + 16 * mt + 8 * rr + gid;
                int j    = jt + row;
                int rowj = b * NN + j;
                float mj = __ldg(&mask[rowj]);
                float me = mi * mj;
                float part = 0.f;
                float* outp = &eout[((size_t)rowi * NN + j) * 64];
                #pragma unroll
                for (int nt = 0; nt < 4; nt++) {
                    int d0 = wcol + 8 * nt + 2 * tig;
                    float2 nj = *(const float2*)&g_Nj[rowj * 64 + d0];
                    float2 kv = *(const float2*)&g_K [rowj * 64 + d0];
                    float e0 = (acc[mt][nt][2 * rr    ] + ni2[nt].x + nj.x) * me;
                    float e1 = (acc[mt][nt][2 * rr + 1] + ni2[nt].y + nj.y) * me;
                    __stcs((float2*)(outp + d0), make_float2(e0, e1));
                    part += q2[nt].x * kv.x * e0 + q2[nt].y * kv.y * e1;
                }
                part += __shfl_xor_sync(0xffffffffu, part, 1);
                part += __shfl_xor_sync(0xffffffffu, part, 2);
                if (tig == 0) pSm[row * 2 + (w & 1)] = part;
            }
        }
        __syncthreads();
        if (tid < 128) {
            int j = jt + tid, rowj = b * NN + j;
            float me = mi * mask[rowj];
            g_A[(size_t)rowi * NN + j] =
                (me > 0.f) ? (pSm[tid * 2] + pSm[tid * 2 + 1]) * 0.125f : -1.0e9f;
        }
        __syncthreads();
    }
}

// ---------------------------------------------------------------------------
// Kernel 3: softmax over axis=1 (over i, per (b,j) column) -> max + 1/sumexp.
// ---------------------------------------------------------------------------
__global__ void colstats_kernel()
{
    int b  = blockIdx.y;
    int j  = blockIdx.x * 32 + threadIdx.x;
    int ty = threadIdx.y;
    const float* A = g_A + (size_t)b * NN * NN;

    float m = -1e30f;
    for (int i = ty; i < NN; i += 8) m = fmaxf(m, A[(size_t)i * NN + j]);
    float s = 0.f;
    for (int i = ty; i < NN; i += 8) s += __expf(A[(size_t)i * NN + j] - m);

    __shared__ float sm[8][32], ss[8][32];
    sm[ty][threadIdx.x] = m;
    ss[ty][threadIdx.x] = s;
    __syncthreads();
    if (ty == 0) {
        float M = sm[0][threadIdx.x];
        #pragma unroll
        for (int t = 1; t < 8; t++) M = fmaxf(M, sm[t][threadIdx.x]);
        float S = 0.f;
        #pragma unroll
        for (int t = 0; t < 8; t++) S += ss[t][threadIdx.x] * __expf(sm[t][threadIdx.x] - M);
        g_M[b * NN + j] = M;
        g_R[b * NN + j] = 1.0f / S;
    }
}

// ---------------------------------------------------------------------------
// Kernel 4: x_out[b,i,:] = sum_j (exp(A-M_j)*R_j) * V[b,j,:], masked.
// 256 threads / block, 4 i-rows per block.
// ---------------------------------------------------------------------------
__global__ __launch_bounds__(256) void xout_kernel(
    const float* __restrict__ mask, float* __restrict__ xout)
{
    int b  = blockIdx.y;
    int r  = threadIdx.x >> 6;
    int tx = threadIdx.x & 63;
    int i  = blockIdx.x * 4 + r;
    __shared__ float pS[4][NN];
    const float* Arow = g_A + ((size_t)(b * NN + i)) * NN;
    for (int jj = tx; jj < NN; jj += 64)
        pS[r][jj] = __expf(Arow[jj] - g_M[b * NN + jj]) * g_R[b * NN + jj];
    __syncthreads();

    float a0 = 0.f, a1 = 0.f, a2 = 0.f, a3 = 0.f;
    const float* Vb = g_V + (size_t)b * NN * 64;
    for (int j = 0; j < NN; j += 4) {
        a0 += pS[r][j    ] * __ldg(&Vb[(j    ) * 64 + tx]);
        a1 += pS[r][j + 1] * __ldg(&Vb[(j + 1) * 64 + tx]);
        a2 += pS[r][j + 2] * __ldg(&Vb[(j + 2) * 64 + tx]);
        a3 += pS[r][j + 3] * __ldg(&Vb[(j + 3) * 64 + tx]);
    }
    xout[(size_t)(b * NN + i) * 64 + tx] = (a0 + a1 + a2 + a3) * mask[b * NN + i];
}

// ---------------------------------------------------------------------------
extern "C" void kernel_launch(void* const* d_in, const int* in_sizes, int n_in,
                              void* d_out, int out_size)
{
    const float* x    = (const float*)d_in[0];
    const float* e    = (const float*)d_in[1];
    const float* mask = (const float*)d_in[2];
    const float* Wq   = (const float*)d_in[3];
    const float* bq   = (const float*)d_in[4];
    const float* Wk   = (const float*)d_in[5];
    const float* bk   = (const float*)d_in[6];
    const float* We   = (const float*)d_in[7];
    const float* be   = (const float*)d_in[8];
    const float* Wv   = (const float*)d_in[9];
    const float* bv   = (const float*)d_in[10];
    const float* Wni  = (const float*)d_in[11];
    const float* bni  = (const float*)d_in[12];
    const float* Wnj  = (const float*)d_in[13];
    const float* bnj  = (const float*)d_in[14];

    float* xout = (float*)d_out;
    float* eout = (float*)d_out + (size_t)BB * NN * DH;

    proj_kernel<<<(BB * NN) / 4, 320>>>(x, mask, Wq, bq, Wk, bk, Wv, bv,
                                        Wni, bni, Wnj, bnj, be);

    prep_we_kernel<<<(DD * WPAD) / 128, 128>>>(We);

    cudaFuncSetAttribute(fused_mma_kernel,
                         cudaFuncAttributeMaxDynamicSharedMemorySize, SMEM_BYTES);
    fused_mma_kernel<<<dim3(NN, BB), 256, SMEM_BYTES>>>(e, mask, eout);

    colstats_kernel<<<dim3(NN / 32, BB), dim3(32, 8)>>>();

    xout_kernel<<<dim3(NN / 4, BB), 256>>>(mask, xout);
}

// round 11
// speedup vs baseline: 1.6223x; 1.1316x over previous
#include <cuda_runtime.h>
#include <cstdint>
#include <cstddef>

#define BB 4
#define NN 512
#define DD 128
#define DH 64

// Scratch (no allocations allowed -> __device__ globals)
__device__ float g_Q [BB*NN*DH];
__device__ float g_K [BB*NN*DH];
__device__ float g_V [BB*NN*DH];
__device__ float g_Ni[BB*NN*DH];
__device__ float g_Nj[BB*NN*DH];
__device__ float g_A [BB*NN*NN];
__device__ float g_M [BB*NN];
__device__ float g_R [BB*NN];

// We^T prepared: tf32(RN) bits, padded layout [128 rows (c)][72 cols (d, 64 used)]
#define WPAD 72
__device__ float g_WeB[DD * WPAD];

// ============================ helpers ============================
__device__ __forceinline__ uint32_t smem_u32(const void* p) {
    uint32_t a;
    asm("{ .reg .u64 t; cvta.to.shared.u64 t, %1; cvt.u32.u64 %0, t; }" : "=r"(a) : "l"(p));
    return a;
}
__device__ __forceinline__ void cp16(uint32_t dst, const void* src) {
    asm volatile("cp.async.cg.shared.global [%0], [%1], 16;" :: "r"(dst), "l"(src));
}
__device__ __forceinline__ uint32_t tf32_rna(float x) {
    uint32_t u;
    asm("cvt.rna.tf32.f32 %0, %1;" : "=r"(u) : "f"(x));
    return u;
}
__device__ __forceinline__ void mma_tf32(float& d0, float& d1, float& d2, float& d3,
                                         uint32_t a0, uint32_t a1, uint32_t a2, uint32_t a3,
                                         uint32_t b0, uint32_t b1) {
    asm volatile(
        "mma.sync.aligned.m16n8k8.row.col.f32.tf32.tf32.f32 "
        "{%0,%1,%2,%3}, {%4,%5,%6,%7}, {%8,%9}, {%0,%1,%2,%3};"
        : "+f"(d0), "+f"(d1), "+f"(d2), "+f"(d3)
        : "r"(a0), "r"(a1), "r"(a2), "r"(a3), "r"(b0), "r"(b1));
}

// ---------------------------------------------------------------------------
// Kernel 1: Q/K/V/Ni/Nj projections (Ni absorbs be).
// ---------------------------------------------------------------------------
__global__ __launch_bounds__(320) void proj_kernel(
    const float* __restrict__ x, const float* __restrict__ mask,
    const float* __restrict__ Wq, const float* __restrict__ bq,
    const float* __restrict__ Wk, const float* __restrict__ bk,
    const float* __restrict__ Wv, const float* __restrict__ bv,
    const float* __restrict__ Wni, const float* __restrict__ bni,
    const float* __restrict__ Wnj, const float* __restrict__ bnj,
    const float* __restrict__ be)
{
    __shared__ float xS[4][DD];
    int r0  = blockIdx.x * 4;
    int tid = threadIdx.x;
    for (int idx = tid; idx < 4 * DD; idx += 320)
        xS[idx >> 7][idx & 127] = x[r0 * DD + idx];
    __syncthreads();

    int mat = tid / 64;
    int d   = tid & 63;
    const float* W; float bias; float* dst; bool domask;
    switch (mat) {
        case 0:  W = Wq;  bias = bq[d];            dst = g_Q;  domask = true;  break;
        case 1:  W = Wk;  bias = bk[d];            dst = g_K;  domask = true;  break;
        case 2:  W = Wv;  bias = bv[d];            dst = g_V;  domask = true;  break;
        case 3:  W = Wni; bias = bni[d] + be[d];   dst = g_Ni; domask = false; break;
        default: W = Wnj; bias = bnj[d];           dst = g_Nj; domask = false; break;
    }
    float a0 = bias, a1 = bias, a2 = bias, a3 = bias;
    #pragma unroll 8
    for (int c = 0; c < DD; c++) {
        float wv = __ldg(&W[c * 64 + d]);
        a0 += xS[0][c] * wv;
        a1 += xS[1][c] * wv;
        a2 += xS[2][c] * wv;
        a3 += xS[3][c] * wv;
    }
    float acc[4] = {a0, a1, a2, a3};
    #pragma unroll
    for (int r = 0; r < 4; r++) {
        int row = r0 + r;
        float m = domask ? mask[row] : 1.0f;
        dst[row * 64 + d] = acc[r] * m;
    }
}

// ---------------------------------------------------------------------------
// Kernel 1b: We -> g_WeB: tf32-RN rounded, padded [128][72] (zero pad).
// ---------------------------------------------------------------------------
__global__ void prep_we_kernel(const float* __restrict__ We)
{
    int idx = blockIdx.x * 128 + threadIdx.x;     // 0 .. 9215
    int row = idx / WPAD;                          // c
    int col = idx - row * WPAD;                    // d (padded)
    uint32_t bits = 0;
    if (col < DH) bits = tf32_rna(We[row * DH + col]);
    g_WeB[idx] = __uint_as_float(bits);
}

// ---------------------------------------------------------------------------
// Kernel 2: fused  E = e@We (tf32 mma.sync) -> e_out + logits.
// One CTA per (b,i). 256 thr = 8 warps. TILE = 64 j-rows (8 tiles), double
// buffered: smem = 102.5 KB -> 2 CTAs/SM (4 warps/SMSP) so one CTA's MMA
// mainloop overlaps the other's loads/epilogue/syncs (tensor pipe stays fed).
// Warp w owns rows [(w>>1)*16,+16), cols [(w&1)*32,+32) of each 64x64 tile.
// A pad 132, B (We) pad 72: conflict-free fragment loads.
// ---------------------------------------------------------------------------
#define APAD 132
#define TILE_R 64
#define OFF_WE   0
#define OFF_A0   (DD * WPAD)                       // 9216
#define OFF_A1   (OFF_A0 + TILE_R * APAD)          // 17664
#define OFF_PS   (OFF_A1 + TILE_R * APAD)          // 26112
#define SMEM_FLOATS (OFF_PS + 128)                 // 26240
#define SMEM_BYTES  (SMEM_FLOATS * 4)              // 104960

// 64x128 f32 tile (32 KB). 256 threads: warp covers one full 512B row
// (32 x cp16), 8 rows per pass, 8 passes.
__device__ __forceinline__ void load_tile(uint32_t dstbase, const float* __restrict__ src0,
                                          int tid)
{
    int c4 = tid & 31;          // float4 index within 512B row (0..31)
    int r0 = tid >> 5;          // 0..7
    const float* s = src0 + c4 * 4;
    #pragma unroll
    for (int k = 0; k < 8; k++) {
        int r = r0 + 8 * k;
        cp16(dstbase + (uint32_t)(r * APAD + c4 * 4) * 4, s + (size_t)r * DD);
    }
}

__global__ void __launch_bounds__(256, 2) fused_mma_kernel(
    const float* __restrict__ e, const float* __restrict__ mask,
    float* __restrict__ eout)
{
    extern __shared__ float smf[];
    float* WeS = smf + OFF_WE;
    float* pSm = smf + OFF_PS;                     // [64][2]
    uint32_t sb = smem_u32(smf);

    int tid  = threadIdx.x;
    int w    = tid >> 5, lane = tid & 31;
    int gid  = lane >> 2, tig = lane & 3;
    int wrow = (w >> 1) * 16;                      // 0,16,32,48
    int wcol = (w & 1) * 32;

    int b = blockIdx.y, i = blockIdx.x;
    int rowi = b * NN + i;
    float mi = mask[rowi];

    // per-thread Q / Ni for its 8 owned columns
    float2 q2[4], ni2[4];
    #pragma unroll
    for (int nt = 0; nt < 4; nt++) {
        int d0 = wcol + 8 * nt + 2 * tig;
        q2[nt]  = *(const float2*)&g_Q [rowi * 64 + d0];
        ni2[nt] = *(const float2*)&g_Ni[rowi * 64 + d0];
    }

    // stage We (9216 floats = 2304 float4; 9 per thread) + tile 0 (group 0)
    {
        const char* wsrc = (const char*)g_WeB;
        #pragma unroll
        for (int k = 0; k < 9; k++) {
            uint32_t off = (uint32_t)(tid + k * 256) * 16;
            cp16(sb + OFF_WE * 4 + off, wsrc + off);
        }
    }
    const float* esrc = e + (size_t)rowi * NN * DD;
    load_tile(sb + OFF_A0 * 4, esrc, tid);
    asm volatile("cp.async.commit_group;" ::: "memory");

    #pragma unroll 1
    for (int t = 0; t < 8; t++) {
        if (t < 7) {
            load_tile(sb + (((t + 1) & 1) ? OFF_A1 : OFF_A0) * 4,
                      esrc + (size_t)(t + 1) * TILE_R * DD, tid);
            asm volatile("cp.async.commit_group;" ::: "memory");
            asm volatile("cp.async.wait_group 1;" ::: "memory");
        } else {
            asm volatile("cp.async.wait_group 0;" ::: "memory");
        }
        __syncthreads();

        const float* A  = smf + ((t & 1) ? OFF_A1 : OFF_A0);
        const float* Ab = A + (wrow + gid) * APAD + tig;   // row gid, col tig
        const float* Bb = WeS + tig * WPAD + wcol + gid;   // k tig, n gid

        float acc[4][4];
        #pragma unroll
        for (int nt = 0; nt < 4; nt++)
            #pragma unroll
            for (int q = 0; q < 4; q++) acc[nt][q] = 0.f;

        #pragma unroll
        for (int ks = 0; ks < 16; ks++) {
            const int c0 = 8 * ks;
            const float* p = Ab + c0;
            uint32_t aR[4];
            aR[0] = tf32_rna(p[0]);
            aR[1] = tf32_rna(p[8 * APAD]);
            aR[2] = tf32_rna(p[4]);
            aR[3] = tf32_rna(p[8 * APAD + 4]);
            uint32_t bR[4][2];
            #pragma unroll
            for (int nt = 0; nt < 4; nt++) {
                const float* pb = Bb + c0 * WPAD + 8 * nt;
                bR[nt][0] = __float_as_uint(pb[0]);
                bR[nt][1] = __float_as_uint(pb[4 * WPAD]);
            }
            #pragma unroll
            for (int nt = 0; nt < 4; nt++)
                mma_tf32(acc[nt][0], acc[nt][1], acc[nt][2], acc[nt][3],
                         aR[0], aR[1], aR[2], aR[3],
                         bR[nt][0], bR[nt][1]);
        }

        // ---- epilogue on fragments ----
        int jt = t * TILE_R;
        #pragma unroll
        for (int rr = 0; rr < 2; rr++) {
            int row  = wrow + 8 * rr + gid;
            int j    = jt + row;
            int rowj = b * NN + j;
            float mj = __ldg(&mask[rowj]);
            float me = mi * mj;
            float part = 0.f;
            float* outp = &eout[((size_t)rowi * NN + j) * 64];
            #pragma unroll
            for (int nt = 0; nt < 4; nt++) {
                int d0 = wcol + 8 * nt + 2 * tig;
                float2 nj = *(const float2*)&g_Nj[rowj * 64 + d0];
                float2 kv = *(const float2*)&g_K [rowj * 64 + d0];
                float e0 = (acc[nt][2 * rr    ] + ni2[nt].x + nj.x) * me;
                float e1 = (acc[nt][2 * rr + 1] + ni2[nt].y + nj.y) * me;
                __stcs((float2*)(outp + d0), make_float2(e0, e1));
                part += q2[nt].x * kv.x * e0 + q2[nt].y * kv.y * e1;
            }
            part += __shfl_xor_sync(0xffffffffu, part, 1);
            part += __shfl_xor_sync(0xffffffffu, part, 2);
            if (tig == 0) pSm[row * 2 + (w & 1)] = part;
        }
        __syncthreads();
        if (tid < TILE_R) {
            int j = jt + tid, rowj = b * NN + j;
            float me = mi * mask[rowj];
            g_A[(size_t)rowi * NN + j] =
                (me > 0.f) ? (pSm[tid * 2] + pSm[tid * 2 + 1]) * 0.125f : -1.0e9f;
        }
        __syncthreads();
    }
}

// ---------------------------------------------------------------------------
// Kernel 3: softmax over axis=1 (over i, per (b,j) column) -> max + 1/sumexp.
// ---------------------------------------------------------------------------
__global__ void colstats_kernel()
{
    int b  = blockIdx.y;
    int j  = blockIdx.x * 32 + threadIdx.x;
    int ty = threadIdx.y;
    const float* A = g_A + (size_t)b * NN * NN;

    float m = -1e30f;
    for (int i = ty; i < NN; i += 8) m = fmaxf(m, A[(size_t)i * NN + j]);
    float s = 0.f;
    for (int i = ty; i < NN; i += 8) s += __expf(A[(size_t)i * NN + j] - m);

    __shared__ float sm[8][32], ss[8][32];
    sm[ty][threadIdx.x] = m;
    ss[ty][threadIdx.x] = s;
    __syncthreads();
    if (ty == 0) {
        float M = sm[0][threadIdx.x];
        #pragma unroll
        for (int t = 1; t < 8; t++) M = fmaxf(M, sm[t][threadIdx.x]);
        float S = 0.f;
        #pragma unroll
        for (int t = 0; t < 8; t++) S += ss[t][threadIdx.x] * __expf(sm[t][threadIdx.x] - M);
        g_M[b * NN + j] = M;
        g_R[b * NN + j] = 1.0f / S;
    }
}

// ---------------------------------------------------------------------------
// Kernel 4: x_out[b,i,:] = sum_j (exp(A-M_j)*R_j) * V[b,j,:], masked.
// 256 threads / block, 4 i-rows per block.
// ---------------------------------------------------------------------------
__global__ __launch_bounds__(256) void xout_kernel(
    const float* __restrict__ mask, float* __restrict__ xout)
{
    int b  = blockIdx.y;
    int r  = threadIdx.x >> 6;
    int tx = threadIdx.x & 63;
    int i  = blockIdx.x * 4 + r;
    __shared__ float pS[4][NN];
    const float* Arow = g_A + ((size_t)(b * NN + i)) * NN;
    for (int jj = tx; jj < NN; jj += 64)
        pS[r][jj] = __expf(Arow[jj] - g_M[b * NN + jj]) * g_R[b * NN + jj];
    __syncthreads();

    float a0 = 0.f, a1 = 0.f, a2 = 0.f, a3 = 0.f;
    const float* Vb = g_V + (size_t)b * NN * 64;
    for (int j = 0; j < NN; j += 4) {
        a0 += pS[r][j    ] * __ldg(&Vb[(j    ) * 64 + tx]);
        a1 += pS[r][j + 1] * __ldg(&Vb[(j + 1) * 64 + tx]);
        a2 += pS[r][j + 2] * __ldg(&Vb[(j + 2) * 64 + tx]);
        a3 += pS[r][j + 3] * __ldg(&Vb[(j + 3) * 64 + tx]);
    }
    xout[(size_t)(b * NN + i) * 64 + tx] = (a0 + a1 + a2 + a3) * mask[b * NN + i];
}

// ---------------------------------------------------------------------------
extern "C" void kernel_launch(void* const* d_in, const int* in_sizes, int n_in,
                              void* d_out, int out_size)
{
    const float* x    = (const float*)d_in[0];
    const float* e    = (const float*)d_in[1];
    const float* mask = (const float*)d_in[2];
    const float* Wq   = (const float*)d_in[3];
    const float* bq   = (const float*)d_in[4];
    const float* Wk   = (const float*)d_in[5];
    const float* bk   = (const float*)d_in[6];
    const float* We   = (const float*)d_in[7];
    const float* be   = (const float*)d_in[8];
    const float* Wv   = (const float*)d_in[9];
    const float* bv   = (const float*)d_in[10];
    const float* Wni  = (const float*)d_in[11];
    const float* bni  = (const float*)d_in[12];
    const float* Wnj  = (const float*)d_in[13];
    const float* bnj  = (const float*)d_in[14];

    float* xout = (float*)d_out;
    float* eout = (float*)d_out + (size_t)BB * NN * DH;

    proj_kernel<<<(BB * NN) / 4, 320>>>(x, mask, Wq, bq, Wk, bk, Wv, bv,
                                        Wni, bni, Wnj, bnj, be);

    prep_we_kernel<<<(DD * WPAD) / 128, 128>>>(We);

    cudaFuncSetAttribute(fused_mma_kernel,
                         cudaFuncAttributeMaxDynamicSharedMemorySize, SMEM_BYTES);
    fused_mma_kernel<<<dim3(NN, BB), 256, SMEM_BYTES>>>(e, mask, eout);

    colstats_kernel<<<dim3(NN / 32, BB), dim3(32, 8)>>>();

    xout_kernel<<<dim3(NN / 4, BB), 256>>>(mask, xout);
}

// round 12
// speedup vs baseline: 2.1185x; 1.3059x over previous
#include <cuda_runtime.h>
#include <cstdint>
#include <cstddef>

#define BB 4
#define NN 512
#define DD 128
#define DH 64

// Scratch (no allocations allowed -> __device__ globals)
__device__ float g_Q [BB*NN*DH];
__device__ float g_K [BB*NN*DH];
__device__ float g_V [BB*NN*DH];
__device__ float g_Ni[BB*NN*DH];
__device__ float g_Nj[BB*NN*DH];
__device__ float g_A [BB*NN*NN];
__device__ float g_M [BB*NN];
__device__ float g_R [BB*NN];

// We^T packed fp16: g_WeH[k2*72 + n] = half2(We[2k2][n] lo, We[2k2+1][n] hi)
// k2 = 0..63 (pairs of k), n = 0..63 (+pad to 72 for conflict-free LDS)
#define WH_STRIDE 72
__device__ uint32_t g_WeH[64 * WH_STRIDE];

// ============================ helpers ============================
__device__ __forceinline__ uint32_t smem_u32(const void* p) {
    uint32_t a;
    asm("{ .reg .u64 t; cvta.to.shared.u64 t, %1; cvt.u32.u64 %0, t; }" : "=r"(a) : "l"(p));
    return a;
}
__device__ __forceinline__ void cp16(uint32_t dst, const void* src) {
    asm volatile("cp.async.cg.shared.global [%0], [%1], 16;" :: "r"(dst), "l"(src));
}
// pack two f32 -> f16x2 (RN): h0 = lo, h1 = hi
__device__ __forceinline__ uint32_t ph2(float lo, float hi) {
    uint32_t u;
    asm("cvt.rn.f16x2.f32 %0, %1, %2;" : "=r"(u) : "f"(hi), "f"(lo));
    return u;
}
__device__ __forceinline__ void mma_f16(float& d0, float& d1, float& d2, float& d3,
                                        uint32_t a0, uint32_t a1, uint32_t a2, uint32_t a3,
                                        uint32_t b0, uint32_t b1) {
    asm volatile(
        "mma.sync.aligned.m16n8k16.row.col.f32.f16.f16.f32 "
        "{%0,%1,%2,%3}, {%4,%5,%6,%7}, {%8,%9}, {%0,%1,%2,%3};"
        : "+f"(d0), "+f"(d1), "+f"(d2), "+f"(d3)
        : "r"(a0), "r"(a1), "r"(a2), "r"(a3), "r"(b0), "r"(b1));
}

// ---------------------------------------------------------------------------
// Kernel 1: Q/K/V/Ni/Nj projections (Ni absorbs be).
// ---------------------------------------------------------------------------
__global__ __launch_bounds__(320) void proj_kernel(
    const float* __restrict__ x, const float* __restrict__ mask,
    const float* __restrict__ Wq, const float* __restrict__ bq,
    const float* __restrict__ Wk, const float* __restrict__ bk,
    const float* __restrict__ Wv, const float* __restrict__ bv,
    const float* __restrict__ Wni, const float* __restrict__ bni,
    const float* __restrict__ Wnj, const float* __restrict__ bnj,
    const float* __restrict__ be)
{
    __shared__ float xS[4][DD];
    int r0  = blockIdx.x * 4;
    int tid = threadIdx.x;
    for (int idx = tid; idx < 4 * DD; idx += 320)
        xS[idx >> 7][idx & 127] = x[r0 * DD + idx];
    __syncthreads();

    int mat = tid / 64;
    int d   = tid & 63;
    const float* W; float bias; float* dst; bool domask;
    switch (mat) {
        case 0:  W = Wq;  bias = bq[d];            dst = g_Q;  domask = true;  break;
        case 1:  W = Wk;  bias = bk[d];            dst = g_K;  domask = true;  break;
        case 2:  W = Wv;  bias = bv[d];            dst = g_V;  domask = true;  break;
        case 3:  W = Wni; bias = bni[d] + be[d];   dst = g_Ni; domask = false; break;
        default: W = Wnj; bias = bnj[d];           dst = g_Nj; domask = false; break;
    }
    float a0 = bias, a1 = bias, a2 = bias, a3 = bias;
    #pragma unroll 8
    for (int c = 0; c < DD; c++) {
        float wv = __ldg(&W[c * 64 + d]);
        a0 += xS[0][c] * wv;
        a1 += xS[1][c] * wv;
        a2 += xS[2][c] * wv;
        a3 += xS[3][c] * wv;
    }
    float acc[4] = {a0, a1, a2, a3};
    #pragma unroll
    for (int r = 0; r < 4; r++) {
        int row = r0 + r;
        float m = domask ? mask[row] : 1.0f;
        dst[row * 64 + d] = acc[r] * m;
    }
}

// ---------------------------------------------------------------------------
// Kernel 1b: We -> g_WeH: fp16-RN, k-adjacent half2 pairs, [64][72] padded.
// ---------------------------------------------------------------------------
__global__ void prep_weh_kernel(const float* __restrict__ We)
{
    int idx = blockIdx.x * 128 + threadIdx.x;     // 0 .. 4607
    int k2 = idx / WH_STRIDE;
    int n  = idx - k2 * WH_STRIDE;
    uint32_t val = 0;
    if (n < DH)
        val = ph2(We[(2 * k2) * DH + n], We[(2 * k2 + 1) * DH + n]);
    g_WeH[idx] = val;
}

// ---------------------------------------------------------------------------
// Kernel 2: fused  E = e@We (fp16 m16n8k16 mma.sync) -> e_out + logits.
// One CTA per (b,i). 256 thr = 8 warps, 2 CTAs/SM. TILE = 64 j-rows, double
// buffered f32 A tiles (APAD=136: conflict-free LDS.64 frag loads).
// Warp w: rows [(w>>1)*16,+16), cols [(w&1)*32,+32). Epilogue operands
// (g_Nj/g_K/mask) prefetched into registers before the MMA loop.
// ---------------------------------------------------------------------------
#define APAD 136
#define TILE_R 64
#define OFF_WE   0                                  // 4608 u32
#define OFF_A0   4608
#define OFF_A1   (OFF_A0 + TILE_R * APAD)           // 13312
#define OFF_PS   (OFF_A1 + TILE_R * APAD)           // 22016 (2 x 64 x 2)
#define SMEM_FLOATS (OFF_PS + 256)                  // 22272
#define SMEM_BYTES  (SMEM_FLOATS * 4)               // 89088

// 64x128 f32 tile (32 KB eff). 256 threads: warp covers one 512B row
// (32 x cp16), 8 rows per pass, 8 passes.
__device__ __forceinline__ void load_tile(uint32_t dstbase, const float* __restrict__ src0,
                                          int tid)
{
    int c4 = tid & 31;          // float4 index within 512B row (0..31)
    int r0 = tid >> 5;          // 0..7
    const float* s = src0 + c4 * 4;
    #pragma unroll
    for (int k = 0; k < 8; k++) {
        int r = r0 + 8 * k;
        cp16(dstbase + (uint32_t)(r * APAD + c4 * 4) * 4, s + (size_t)r * DD);
    }
}

__global__ void __launch_bounds__(256, 2) fused_mma_kernel(
    const float* __restrict__ e, const float* __restrict__ mask,
    float* __restrict__ eout)
{
    extern __shared__ float smf[];
    uint32_t* WeHS = reinterpret_cast<uint32_t*>(smf + OFF_WE);
    float*    pSm  = smf + OFF_PS;                 // [2][64][2]
    uint32_t  sb   = smem_u32(smf);

    int tid  = threadIdx.x;
    int w    = tid >> 5, lane = tid & 31;
    int gid  = lane >> 2, tig = lane & 3;
    int wrow = (w >> 1) * 16;                      // 0,16,32,48
    int wcol = (w & 1) * 32;

    int b = blockIdx.y, i = blockIdx.x;
    int rowi = b * NN + i;
    float mi = mask[rowi];

    // per-thread Q / Ni for its 8 owned columns
    float2 q2[4], ni2[4];
    #pragma unroll
    for (int nt = 0; nt < 4; nt++) {
        int d0 = wcol + 8 * nt + 2 * tig;
        q2[nt]  = *(const float2*)&g_Q [rowi * 64 + d0];
        ni2[nt] = *(const float2*)&g_Ni[rowi * 64 + d0];
    }

    // stage WeH (4608 u32 = 1152 x 16B) + tile 0 into cp.async group 0
    {
        const char* wsrc = (const char*)g_WeH;
        #pragma unroll
        for (int k = 0; k < 5; k++) {
            int idx = tid + k * 256;
            if (idx < 1152)
                cp16(sb + OFF_WE * 4 + (uint32_t)idx * 16, wsrc + (size_t)idx * 16);
        }
    }
    const float* esrc = e + (size_t)rowi * NN * DD;
    load_tile(sb + OFF_A0 * 4, esrc, tid);
    asm volatile("cp.async.commit_group;" ::: "memory");

    #pragma unroll 1
    for (int t = 0; t < 8; t++) {
        int jt = t * TILE_R;

        // ---- prefetch epilogue operands for this tile (hidden behind MMA) ----
        float2 njR[2][4], kvR[2][4];
        float  mjR[2];
        #pragma unroll
        for (int rr = 0; rr < 2; rr++) {
            int rowj = b * NN + jt + wrow + 8 * rr + gid;
            mjR[rr] = __ldg(&mask[rowj]);
            #pragma unroll
            for (int nt = 0; nt < 4; nt++) {
                int d0 = wcol + 8 * nt + 2 * tig;
                njR[rr][nt] = *(const float2*)&g_Nj[rowj * 64 + d0];
                kvR[rr][nt] = *(const float2*)&g_K [rowj * 64 + d0];
            }
        }

        if (t < 7) {
            load_tile(sb + (((t + 1) & 1) ? OFF_A1 : OFF_A0) * 4,
                      esrc + (size_t)(t + 1) * TILE_R * DD, tid);
            asm volatile("cp.async.commit_group;" ::: "memory");
            asm volatile("cp.async.wait_group 1;" ::: "memory");
        } else {
            asm volatile("cp.async.wait_group 0;" ::: "memory");
        }
        __syncthreads();

        const float*    A  = smf + ((t & 1) ? OFF_A1 : OFF_A0);
        const float*    Ab = A + (wrow + gid) * APAD + 2 * tig;
        const uint32_t* Bb = WeHS + tig * WH_STRIDE + wcol + gid;

        float acc[4][4];
        #pragma unroll
        for (int nt = 0; nt < 4; nt++)
            #pragma unroll
            for (int q = 0; q < 4; q++) acc[nt][q] = 0.f;

        #pragma unroll
        for (int ks = 0; ks < 8; ks++) {          // K16 chunks
            const float* pA = Ab + 16 * ks;
            float2 f0 = *(const float2*)(pA);
            float2 f1 = *(const float2*)(pA + 8 * APAD);
            float2 f2 = *(const float2*)(pA + 8);
            float2 f3 = *(const float2*)(pA + 8 * APAD + 8);
            uint32_t a0 = ph2(f0.x, f0.y);
            uint32_t a1 = ph2(f1.x, f1.y);
            uint32_t a2 = ph2(f2.x, f2.y);
            uint32_t a3 = ph2(f3.x, f3.y);
            const uint32_t* pB = Bb + 8 * ks * WH_STRIDE;
            #pragma unroll
            for (int nt = 0; nt < 4; nt++) {
                uint32_t b0 = pB[8 * nt];
                uint32_t b1 = pB[4 * WH_STRIDE + 8 * nt];
                mma_f16(acc[nt][0], acc[nt][1], acc[nt][2], acc[nt][3],
                        a0, a1, a2, a3, b0, b1);
            }
        }

        // ---- epilogue on fragments (all operands already in registers) ----
        float* pBuf = pSm + (t & 1) * 128;
        #pragma unroll
        for (int rr = 0; rr < 2; rr++) {
            int row  = wrow + 8 * rr + gid;
            int j    = jt + row;
            float me = mi * mjR[rr];
            float part = 0.f;
            float* outp = &eout[((size_t)rowi * NN + j) * 64];
            #pragma unroll
            for (int nt = 0; nt < 4; nt++) {
                int d0 = wcol + 8 * nt + 2 * tig;
                float e0 = (acc[nt][2 * rr    ] + ni2[nt].x + njR[rr][nt].x) * me;
                float e1 = (acc[nt][2 * rr + 1] + ni2[nt].y + njR[rr][nt].y) * me;
                __stcs((float2*)(outp + d0), make_float2(e0, e1));
                part += q2[nt].x * kvR[rr][nt].x * e0 + q2[nt].y * kvR[rr][nt].y * e1;
            }
            part += __shfl_xor_sync(0xffffffffu, part, 1);
            part += __shfl_xor_sync(0xffffffffu, part, 2);
            if (tig == 0) pBuf[row * 2 + (w & 1)] = part;
        }
        __syncthreads();
        if (tid < TILE_R) {
            int j = jt + tid, rowj = b * NN + j;
            float me = mi * mask[rowj];
            g_A[(size_t)rowi * NN + j] =
                (me > 0.f) ? (pBuf[tid * 2] + pBuf[tid * 2 + 1]) * 0.125f : -1.0e9f;
        }
        // no trailing sync: next tile writes the other pSm buffer; A-buffer
        // reuse is protected by the post-wait __syncthreads above.
    }
}

// ---------------------------------------------------------------------------
// Kernel 3: softmax over axis=1 (over i, per (b,j) column) -> max + 1/sumexp.
// ---------------------------------------------------------------------------
__global__ void colstats_kernel()
{
    int b  = blockIdx.y;
    int j  = blockIdx.x * 32 + threadIdx.x;
    int ty = threadIdx.y;
    const float* A = g_A + (size_t)b * NN * NN;

    float m = -1e30f;
    for (int i = ty; i < NN; i += 8) m = fmaxf(m, A[(size_t)i * NN + j]);
    float s = 0.f;
    for (int i = ty; i < NN; i += 8) s += __expf(A[(size_t)i * NN + j] - m);

    __shared__ float sm[8][32], ss[8][32];
    sm[ty][threadIdx.x] = m;
    ss[ty][threadIdx.x] = s;
    __syncthreads();
    if (ty == 0) {
        float M = sm[0][threadIdx.x];
        #pragma unroll
        for (int t = 1; t < 8; t++) M = fmaxf(M, sm[t][threadIdx.x]);
        float S = 0.f;
        #pragma unroll
        for (int t = 0; t < 8; t++) S += ss[t][threadIdx.x] * __expf(sm[t][threadIdx.x] - M);
        g_M[b * NN + j] = M;
        g_R[b * NN + j] = 1.0f / S;
    }
}

// ---------------------------------------------------------------------------
// Kernel 4: x_out[b,i,:] = sum_j (exp(A-M_j)*R_j) * V[b,j,:], masked.
// 512 threads / block, 8 i-rows per block (V reuse via L1 + occupancy).
// ---------------------------------------------------------------------------
__global__ __launch_bounds__(512) void xout_kernel(
    const float* __restrict__ mask, float* __restrict__ xout)
{
    int b  = blockIdx.y;
    int r  = threadIdx.x >> 6;     // 0..7
    int tx = threadIdx.x & 63;
    int i  = blockIdx.x * 8 + r;
    __shared__ float pS[8][NN];
    const float* Arow = g_A + ((size_t)(b * NN + i)) * NN;
    for (int jj = tx; jj < NN; jj += 64)
        pS[r][jj] = __expf(Arow[jj] - g_M[b * NN + jj]) * g_R[b * NN + jj];
    __syncthreads();

    float a0 = 0.f, a1 = 0.f, a2 = 0.f, a3 = 0.f;
    const float* Vb = g_V + (size_t)b * NN * 64;
    for (int j = 0; j < NN; j += 4) {
        a0 += pS[r][j    ] * __ldg(&Vb[(j    ) * 64 + tx]);
        a1 += pS[r][j + 1] * __ldg(&Vb[(j + 1) * 64 + tx]);
        a2 += pS[r][j + 2] * __ldg(&Vb[(j + 2) * 64 + tx]);
        a3 += pS[r][j + 3] * __ldg(&Vb[(j + 3) * 64 + tx]);
    }
    xout[(size_t)(b * NN + i) * 64 + tx] = (a0 + a1 + a2 + a3) * mask[b * NN + i];
}

// ---------------------------------------------------------------------------
extern "C" void kernel_launch(void* const* d_in, const int* in_sizes, int n_in,
                              void* d_out, int out_size)
{
    const float* x    = (const float*)d_in[0];
    const float* e    = (const float*)d_in[1];
    const float* mask = (const float*)d_in[2];
    const float* Wq   = (const float*)d_in[3];
    const float* bq   = (const float*)d_in[4];
    const float* Wk   = (const float*)d_in[5];
    const float* bk   = (const float*)d_in[6];
    const float* We   = (const float*)d_in[7];
    const float* be   = (const float*)d_in[8];
    const float* Wv   = (const float*)d_in[9];
    const float* bv   = (const float*)d_in[10];
    const float* Wni  = (const float*)d_in[11];
    const float* bni  = (const float*)d_in[12];
    const float* Wnj  = (const float*)d_in[13];
    const float* bnj  = (const float*)d_in[14];

    float* xout = (float*)d_out;
    float* eout = (float*)d_out + (size_t)BB * NN * DH;

    proj_kernel<<<(BB * NN) / 4, 320>>>(x, mask, Wq, bq, Wk, bk, Wv, bv,
                                        Wni, bni, Wnj, bnj, be);

    prep_weh_kernel<<<(64 * WH_STRIDE) / 128, 128>>>(We);

    cudaFuncSetAttribute(fused_mma_kernel,
                         cudaFuncAttributeMaxDynamicSharedMemorySize, SMEM_BYTES);
    fused_mma_kernel<<<dim3(NN, BB), 256, SMEM_BYTES>>>(e, mask, eout);

    colstats_kernel<<<dim3(NN / 32, BB), dim3(32, 8)>>>();

    xout_kernel<<<dim3(NN / 8, BB), 512>>>(mask, xout);
}